// round 16
// baseline (speedup 1.0000x reference)
#include <cuda_runtime.h>
#include <cuda_fp16.h>
#include <math.h>

#define NN 100000
#define EE 1600000
#define DD 128
#define HID 32

typedef unsigned long long ull;

// ---------------- scratch (device globals) ------------------------------------
__device__ int      g_is64;
__device__ int      g_deg[NN];
__device__ float    g_dinv[NN];
__device__ int      g_off[NN + 1];
__device__ int      g_cur[NN];
__device__ int      g_src32[EE];
__device__ int      g_dst32[EE];
__device__ int      g_srcs[EE];             // CSR: prescaled src element offsets (s*32)
__device__ unsigned g_y2h[(size_t)NN * 32]; // half2(z,h) per (node,feature); pre-scaled by dinv
__device__ __half   g_Hh[(size_t)NN * 32];  // H in fp16, 64B rows
__device__ float    g_WT[64 * DD];          // WeffT[j][k], j: 0..31=z, 32..63=h
__device__ ull      g_beff2[32];            // packed (bz_eff, bh_eff) fp32
__device__ unsigned g_part[128];            // decoupled-lookback partials (flag bit 0)

// ---------------- helpers ------------------------------------------------------
__device__ __forceinline__ ull pack2(float a, float b) {
    ull r; asm("mov.b64 %0, {%1, %2};" : "=l"(r) : "f"(a), "f"(b)); return r;
}
__device__ __forceinline__ void unpack2(ull v, float& a, float& b) {
    asm("mov.b64 {%0, %1}, %2;" : "=f"(a), "=f"(b) : "l"(v));
}
__device__ __forceinline__ int edge_at(const void* ei, int is64, long long idx) {
    return is64 ? (int)((const long long*)ei)[idx] : ((const int*)ei)[idx];
}
__device__ __forceinline__ unsigned s2u(const void* p) {
    unsigned a;
    asm("{ .reg .u64 t; cvta.to.shared.u64 t, %1; cvt.u32.u64 %0, t; }" : "=r"(a) : "l"(p));
    return a;
}

// ---------------- prep: detect + deg init + lookback reset + Weff^T -----------
__global__ void k_prep(const void* ei,
                       const float* Wz, const float* Wh,
                       const float* Lzw, const float* Lhw,
                       const float* bz, const float* bh,
                       const float* Lzb, const float* Lhb) {
    int b = blockIdx.x, t = threadIdx.x;
    if (b < 391) {
        int i = b * 256 + t;
        if (i < NN) g_deg[i] = 1;           // self loop
    } else if (b == 391) {
        __shared__ int s;
        if (t == 0) s = 1;
        __syncthreads();
        const long long* p = (const long long*)ei;
        for (int i = t; i < 4096; i += 256)
            if ((p[i] >> 32) != 0) s = 0;
        __syncthreads();
        if (t == 0) g_is64 = s;
        if (t < 128) g_part[t] = 0;         // reset lookback state (graph replay!)
    } else {
        int idx = (b - 392) * 256 + t;      // [0, 8192)
        int k = idx >> 6, j = idx & 63;
        float acc = 0.f;
        if (j < HID) {
            for (int m = 0; m < HID; m++) acc = fmaf(Wz[k * HID + m], Lzw[m * HID + j], acc);
        } else {
            int jj = j - HID;
            for (int m = 0; m < HID; m++) acc = fmaf(Wh[k * HID + m], Lhw[m * HID + jj], acc);
        }
        g_WT[j * DD + k] = acc;             // transposed store [j][k]
        if (b == 392 && t < 32) {
            float az = Lzb[t], ah = Lhb[t];
            for (int m = 0; m < HID; m++) {
                az = fmaf(bz[m], Lzw[m * HID + t], az);
                ah = fmaf(bh[m], Lhw[m * HID + t], ah);
            }
            g_beff2[t] = pack2(az, ah);
        }
    }
}

// ---------------- edge conversion + degree count ------------------------------
__global__ void k_deg(const void* __restrict__ ei) {
    int is64 = g_is64;
    int e = blockIdx.x * 256 + threadIdx.x;
    if (e < EE) {
        int s = edge_at(ei, is64, e);
        int d = edge_at(ei, is64, (long long)EE + e);
        g_src32[e] = s;
        g_dst32[e] = d;
        atomicAdd(&g_deg[d], 1);
    }
}

// ---------------- fused scan: block scan + decoupled lookback + dinv ----------
#define SB 98
__global__ void __launch_bounds__(1024, 1) k_scan() {
    __shared__ int warpsums[32];
    __shared__ unsigned spart[128];
    __shared__ int sprefix;
    int b = blockIdx.x, t = threadIdx.x, lane = t & 31, w = t >> 5;

    int i = b * 1024 + t;
    int dg = (i < NN) ? g_deg[i] : 1;
    if (i < NN) g_dinv[i] = rsqrtf((float)dg);
    int v = dg - 1;
    int s = v;
#pragma unroll
    for (int off = 1; off < 32; off <<= 1) {
        int tmp = __shfl_up_sync(0xffffffffu, s, off);
        if (lane >= off) s += tmp;
    }
    if (lane == 31) warpsums[w] = s;
    __syncthreads();
    if (w == 0) {
        int ws = warpsums[lane];
#pragma unroll
        for (int off = 1; off < 32; off <<= 1) {
            int tmp = __shfl_up_sync(0xffffffffu, ws, off);
            if (lane >= off) ws += tmp;
        }
        warpsums[lane] = ws;
    }
    __syncthreads();
    int incl = s + ((w == 0) ? 0 : warpsums[w - 1]);
    int btotal = warpsums[31];

    // publish block total (flag in bit 0)
    if (t == 0) atomicExch(&g_part[b], ((unsigned)btotal << 1) | 1u);

    // parallel lookback: thread t spins on predecessor t
    if (t < b) {
        unsigned pv;
        do { pv = atomicOr(&g_part[t], 0u); } while (!(pv & 1u));
        spart[t] = pv >> 1;
    } else if (t < 128) {
        spart[t] = 0;
    }
    __syncthreads();
    if (w == 0) {
        unsigned acc = spart[lane] + spart[lane + 32] + spart[lane + 64] + spart[lane + 96];
#pragma unroll
        for (int off = 16; off > 0; off >>= 1)
            acc += __shfl_down_sync(0xffffffffu, acc, off);
        if (lane == 0) sprefix = (int)acc;
    }
    __syncthreads();
    int pref = sprefix;
    if (i < NN) {
        int o = pref + incl - v;
        g_off[i] = o;
        g_cur[i] = o;
    }
    if (b == SB - 1 && t == 1023) g_off[NN] = pref + incl;
}

// ---------------- fused: HMMA node GEMM (blocks [0,GEMMB)) + CSR scatter ------
#define GEMMB 1563              // ceil(6250 warp-tiles / 4 warps per 128-thr block)
#define SCATB 12500
__global__ void __launch_bounds__(128) k_gemm_scat(const float* __restrict__ x) {
    if (blockIdx.x < GEMMB) {
        __shared__ __align__(16) __half sB[64 * 128];     // Weff fp16, swizzled (16KB)
        __shared__ __align__(16) __half sA[4][16 * 128];  // per-warp x tiles (16KB)
        int tid = threadIdx.x, wid = tid >> 5, lane = tid & 31;

        // fill B: g_WT [64][128] fp32 -> fp16 swizzled
        for (int idx = tid; idx < 2048; idx += 128) {     // 2048 float4
            int row = idx >> 5, f4 = idx & 31;
            float4 v = ((const float4*)g_WT)[idx];
            __half2 h0 = __floats2half2_rn(v.x, v.y);
            __half2 h1 = __floats2half2_rn(v.z, v.w);
            unsigned off = (unsigned)(row * 256 + (((f4 >> 1) ^ (row & 7)) << 4) + ((f4 & 1) << 3));
            *(unsigned*)((char*)sB + off)     = *(unsigned*)&h0;
            *(unsigned*)((char*)sB + off + 4) = *(unsigned*)&h1;
        }
        __syncthreads();

        int wt = blockIdx.x * 4 + wid;                    // warp-tile id
        if (wt >= 6250) return;
        int n0 = wt * 16;

        const float4* x4 = (const float4*)x;
#pragma unroll
        for (int ii = 0; ii < 16; ii++) {
            float4 v = x4[(size_t)(n0 + ii) * 32 + lane];
            __half2 h0 = __floats2half2_rn(v.x, v.y);
            __half2 h1 = __floats2half2_rn(v.z, v.w);
            unsigned off = (unsigned)(ii * 256 + (((lane >> 1) ^ (ii & 7)) << 4) + ((lane & 1) << 3));
            *(unsigned*)((char*)sA[wid] + off)     = *(unsigned*)&h0;
            *(unsigned*)((char*)sA[wid] + off + 4) = *(unsigned*)&h1;
        }
        __syncwarp();

        unsigned Af[8][4];
        unsigned sA_u = s2u(sA[wid]);
        {
            int r = lane & 15;
#pragma unroll
            for (int kt = 0; kt < 8; kt++) {
                unsigned chunk = (unsigned)(2 * kt + ((lane & 16) ? 1 : 0));
                unsigned addr = sA_u + (unsigned)(r * 256) + ((chunk ^ (unsigned)(r & 7)) << 4);
                asm volatile("ldmatrix.sync.aligned.m8n8.x4.shared.b16 {%0,%1,%2,%3}, [%4];"
                             : "=r"(Af[kt][0]), "=r"(Af[kt][1]), "=r"(Af[kt][2]), "=r"(Af[kt][3])
                             : "r"(addr));
            }
        }

        unsigned sB_u = s2u(sB);
        int g = lane >> 2, tig = lane & 3;
        int rB = lane & 7;
        unsigned bhalf = (lane & 8) ? 1u : 0u;

#pragma unroll
        for (int p = 0; p < 4; p++) {                     // z cols nt=p, h cols nt=p+4
            float Dz[4] = {0.f, 0.f, 0.f, 0.f};
            float Dh[4] = {0.f, 0.f, 0.f, 0.f};
#pragma unroll
            for (int kt = 0; kt < 8; kt++) {
                unsigned chunk = (unsigned)(2 * kt) + bhalf;
                unsigned swz = ((chunk ^ (unsigned)rB) << 4);
                unsigned az_addr = sB_u + (unsigned)((p * 8 + rB) * 256) + swz;
                unsigned ah_addr = sB_u + (unsigned)(((p + 4) * 8 + rB) * 256) + swz;
                unsigned Bz[2], Bh[2];
                asm volatile("ldmatrix.sync.aligned.m8n8.x2.shared.b16 {%0,%1}, [%2];"
                             : "=r"(Bz[0]), "=r"(Bz[1]) : "r"(az_addr));
                asm volatile("ldmatrix.sync.aligned.m8n8.x2.shared.b16 {%0,%1}, [%2];"
                             : "=r"(Bh[0]), "=r"(Bh[1]) : "r"(ah_addr));
                asm volatile(
                    "mma.sync.aligned.m16n8k16.row.col.f32.f16.f16.f32 "
                    "{%0,%1,%2,%3}, {%4,%5,%6,%7}, {%8,%9}, {%0,%1,%2,%3};"
                    : "+f"(Dz[0]), "+f"(Dz[1]), "+f"(Dz[2]), "+f"(Dz[3])
                    : "r"(Af[kt][0]), "r"(Af[kt][1]), "r"(Af[kt][2]), "r"(Af[kt][3]),
                      "r"(Bz[0]), "r"(Bz[1]));
                asm volatile(
                    "mma.sync.aligned.m16n8k16.row.col.f32.f16.f16.f32 "
                    "{%0,%1,%2,%3}, {%4,%5,%6,%7}, {%8,%9}, {%0,%1,%2,%3};"
                    : "+f"(Dh[0]), "+f"(Dh[1]), "+f"(Dh[2]), "+f"(Dh[3])
                    : "r"(Af[kt][0]), "r"(Af[kt][1]), "r"(Af[kt][2]), "r"(Af[kt][3]),
                      "r"(Bh[0]), "r"(Bh[1]));
            }
            int c0 = p * 8 + tig * 2;
            float dn0 = g_dinv[n0 + g];
            float dn1 = g_dinv[n0 + g + 8];
            __half2 a0 = __floats2half2_rn(Dz[0] * dn0, Dh[0] * dn0);
            __half2 a1 = __floats2half2_rn(Dz[1] * dn0, Dh[1] * dn0);
            __half2 b0 = __floats2half2_rn(Dz[2] * dn1, Dh[2] * dn1);
            __half2 b1 = __floats2half2_rn(Dz[3] * dn1, Dh[3] * dn1);
            unsigned ua0 = *(unsigned*)&a0, ua1 = *(unsigned*)&a1;
            unsigned ub0 = *(unsigned*)&b0, ub1 = *(unsigned*)&b1;
            *(ull*)&g_y2h[(size_t)(n0 + g) * 32 + c0]     = ((ull)ua1 << 32) | ua0;
            *(ull*)&g_y2h[(size_t)(n0 + g + 8) * 32 + c0] = ((ull)ub1 << 32) | ub0;
        }
    } else {
        int e = (blockIdx.x - GEMMB) * 128 + threadIdx.x;
        if (e < EE) {
            int s = g_src32[e], d = g_dst32[e];
            int pos = atomicAdd(&g_cur[d], 1);
            g_srcs[pos] = s * 32;           // prescaled element offset into g_y2h
        }
    }
}

// ---------------- aggregate (fp16 gathers, 4-way ILP) + GRU gates → fp16 H ----
__global__ void k_agg() {
    int warp = (blockIdx.x * blockDim.x + threadIdx.x) >> 5;
    int lane = threadIdx.x & 31;
    if (warp >= NN) return;
    int n = warp;
    unsigned sv = g_y2h[(size_t)n * 32 + lane];     // self term
    float2 f = __half22float2(*(__half2*)&sv);
    float az0 = f.x, ah0 = f.y;
    float az1 = 0.f, ah1 = 0.f, az2 = 0.f, ah2 = 0.f, az3 = 0.f, ah3 = 0.f;
    int beg = g_off[n], end = g_off[n + 1];
    int idx = beg;
    for (; idx + 3 < end; idx += 4) {
        unsigned v0 = g_y2h[g_srcs[idx]     + lane];
        unsigned v1 = g_y2h[g_srcs[idx + 1] + lane];
        unsigned v2 = g_y2h[g_srcs[idx + 2] + lane];
        unsigned v3 = g_y2h[g_srcs[idx + 3] + lane];
        float2 f0 = __half22float2(*(__half2*)&v0);
        float2 f1 = __half22float2(*(__half2*)&v1);
        float2 f2 = __half22float2(*(__half2*)&v2);
        float2 f3 = __half22float2(*(__half2*)&v3);
        az0 += f0.x; ah0 += f0.y;
        az1 += f1.x; ah1 += f1.y;
        az2 += f2.x; ah2 += f2.y;
        az3 += f3.x; ah3 += f3.y;
    }
    for (; idx < end; idx++) {
        unsigned v0 = g_y2h[g_srcs[idx] + lane];
        float2 f0 = __half22float2(*(__half2*)&v0);
        az0 += f0.x; ah0 += f0.y;
    }
    float dn = g_dinv[n];
    float bz, bh;
    unpack2(g_beff2[lane], bz, bh);
    float vz = ((az0 + az1) + (az2 + az3)) * dn + bz;
    float vh = ((ah0 + ah1) + (ah2 + ah3)) * dn + bh;
    float z  = 1.f / (1.f + __expf(-vz));
    float ht = tanhf(vh);
    g_Hh[(size_t)n * 32 + lane] = __float2half((1.f - z) * ht);
}

// ---------------- edge MLP via mma.sync m16n8k16 (R14-proven) -----------------
__global__ void __launch_bounds__(256) k_edge_mma(
        const float* __restrict__ w1, const float* __restrict__ b1,
        const float* __restrict__ w2, const float* __restrict__ b2,
        float* __restrict__ out) {
    __shared__ __align__(16) __half sEmb[8][16][32];
    __shared__ float sb1[32], sw2[32];
    __shared__ float sb2v;
    int tid = threadIdx.x, wid = tid >> 5, lane = tid & 31;
    if (tid < 32) { sb1[tid] = b1[tid]; sw2[tid] = w2[tid]; }
    if (tid == 0) sb2v = b2[0];

    int g = lane >> 2, tig = lane & 3;

    unsigned Bf[2][4][2];
#pragma unroll
    for (int kt = 0; kt < 2; kt++) {
#pragma unroll
        for (int nt = 0; nt < 4; nt++) {
            int n = nt * 8 + g;
            int k0 = kt * 16 + tig * 2;
            __half2 t0 = __floats2half2_rn(w1[k0 * HID + n],       w1[(k0 + 1) * HID + n]);
            __half2 t1 = __floats2half2_rn(w1[(k0 + 8) * HID + n], w1[(k0 + 9) * HID + n]);
            Bf[kt][nt][0] = *(unsigned*)&t0;
            Bf[kt][nt][1] = *(unsigned*)&t1;
        }
    }
    __syncthreads();

    int ebase = (blockIdx.x * 8 + wid) * 16;
    int er = lane >> 1, hf = lane & 1;
    {
        int e = ebase + er;
        int s = g_src32[e], d = g_dst32[e];
        const uint4* Hs = (const uint4*)(g_Hh + (size_t)s * 32) + hf * 2;
        const uint4* Hd = (const uint4*)(g_Hh + (size_t)d * 32) + hf * 2;
        uint4 sa = Hs[0], sbv = Hs[1];
        uint4 da = Hd[0], dbv = Hd[1];
        uint4 r0, r1;
        *(__half2*)&r0.x = __hmul2(*(__half2*)&sa.x, *(__half2*)&da.x);
        *(__half2*)&r0.y = __hmul2(*(__half2*)&sa.y, *(__half2*)&da.y);
        *(__half2*)&r0.z = __hmul2(*(__half2*)&sa.z, *(__half2*)&da.z);
        *(__half2*)&r0.w = __hmul2(*(__half2*)&sa.w, *(__half2*)&da.w);
        *(__half2*)&r1.x = __hmul2(*(__half2*)&sbv.x, *(__half2*)&dbv.x);
        *(__half2*)&r1.y = __hmul2(*(__half2*)&sbv.y, *(__half2*)&dbv.y);
        *(__half2*)&r1.z = __hmul2(*(__half2*)&sbv.z, *(__half2*)&dbv.z);
        *(__half2*)&r1.w = __hmul2(*(__half2*)&sbv.w, *(__half2*)&dbv.w);
        uint4* dst = (uint4*)&sEmb[wid][er][hf * 16];
        dst[0] = r0;
        dst[1] = r1;
    }
    __syncwarp();

    unsigned A0[4], A1[4];
    {
        unsigned base = s2u(&sEmb[wid][lane & 15][(lane & 16) ? 8 : 0]);
        asm volatile("ldmatrix.sync.aligned.m8n8.x4.shared.b16 {%0,%1,%2,%3}, [%4];"
                     : "=r"(A0[0]), "=r"(A0[1]), "=r"(A0[2]), "=r"(A0[3]) : "r"(base));
        asm volatile("ldmatrix.sync.aligned.m8n8.x4.shared.b16 {%0,%1,%2,%3}, [%4];"
                     : "=r"(A1[0]), "=r"(A1[1]), "=r"(A1[2]), "=r"(A1[3]) : "r"(base + 32));
    }

    float D[4][4];
#pragma unroll
    for (int nt = 0; nt < 4; nt++) {
        D[nt][0] = D[nt][1] = D[nt][2] = D[nt][3] = 0.f;
        asm volatile(
            "mma.sync.aligned.m16n8k16.row.col.f32.f16.f16.f32 "
            "{%0,%1,%2,%3}, {%4,%5,%6,%7}, {%8,%9}, {%0,%1,%2,%3};"
            : "+f"(D[nt][0]), "+f"(D[nt][1]), "+f"(D[nt][2]), "+f"(D[nt][3])
            : "r"(A0[0]), "r"(A0[1]), "r"(A0[2]), "r"(A0[3]),
              "r"(Bf[0][nt][0]), "r"(Bf[0][nt][1]));
        asm volatile(
            "mma.sync.aligned.m16n8k16.row.col.f32.f16.f16.f32 "
            "{%0,%1,%2,%3}, {%4,%5,%6,%7}, {%8,%9}, {%0,%1,%2,%3};"
            : "+f"(D[nt][0]), "+f"(D[nt][1]), "+f"(D[nt][2]), "+f"(D[nt][3])
            : "r"(A1[0]), "r"(A1[1]), "r"(A1[2]), "r"(A1[3]),
              "r"(Bf[1][nt][0]), "r"(Bf[1][nt][1]));
    }

    float l0 = 0.f, l1 = 0.f;
#pragma unroll
    for (int nt = 0; nt < 4; nt++) {
        int c0 = nt * 8 + tig * 2;
        float w20 = sw2[c0], w21 = sw2[c0 + 1];
        float bb0 = sb1[c0], bb1 = sb1[c0 + 1];
        l0 = fmaf(fmaxf(D[nt][0] + bb0, 0.f), w20, l0);
        l0 = fmaf(fmaxf(D[nt][1] + bb1, 0.f), w21, l0);
        l1 = fmaf(fmaxf(D[nt][2] + bb0, 0.f), w20, l1);
        l1 = fmaf(fmaxf(D[nt][3] + bb1, 0.f), w21, l1);
    }
    l0 += __shfl_xor_sync(0xffffffffu, l0, 1);
    l0 += __shfl_xor_sync(0xffffffffu, l0, 2);
    l1 += __shfl_xor_sync(0xffffffffu, l1, 1);
    l1 += __shfl_xor_sync(0xffffffffu, l1, 2);
    if (tig == 0) {
        out[ebase + g]     = 1.f / (1.f + __expf(-(l0 + sb2v)));
        out[ebase + g + 8] = 1.f / (1.f + __expf(-(l1 + sb2v)));
    }
}

// ---------------- launch ------------------------------------------------------
extern "C" void kernel_launch(void* const* d_in, const int* in_sizes, int n_in,
                              void* d_out, int out_size) {
    const float* x   = (const float*)d_in[0];
    const void*  ei  = d_in[1];
    const float* Wz  = (const float*)d_in[2];
    const float* bz  = (const float*)d_in[3];
    const float* Wh  = (const float*)d_in[6];
    const float* bh  = (const float*)d_in[7];
    const float* Lzw = (const float*)d_in[8];
    const float* Lzb = (const float*)d_in[9];
    const float* Lhw = (const float*)d_in[12];
    const float* Lhb = (const float*)d_in[13];
    const float* w1  = (const float*)d_in[14];
    const float* b1  = (const float*)d_in[15];
    const float* w2  = (const float*)d_in[16];
    const float* b2  = (const float*)d_in[17];
    float* out = (float*)d_out;

    k_prep<<<424, 256>>>(ei, Wz, Wh, Lzw, Lhw, bz, bh, Lzb, Lhb);
    k_deg<<<6250, 256>>>(ei);
    k_scan<<<SB, 1024>>>();
    k_gemm_scat<<<GEMMB + SCATB, 128>>>(x);
    k_agg<<<(NN * 32 + 255) / 256, 256>>>();
    k_edge_mma<<<EE / 128, 256>>>(w1, b1, w2, b2, out);
}

// round 17
// speedup vs baseline: 1.0383x; 1.0383x over previous
#include <cuda_runtime.h>
#include <cuda_fp16.h>
#include <math.h>

#define NN 100000
#define EE 1600000
#define DD 128
#define HID 32

typedef unsigned long long ull;

// ---------------- scratch (device globals) ------------------------------------
__device__ int      g_is64;
__device__ int      g_deg[NN];
__device__ float    g_dinv[NN];
__device__ int      g_off[NN + 1];
__device__ int      g_cur[NN];
__device__ int      g_src32[EE];
__device__ int      g_dst32[EE];
__device__ int      g_srcs[EE];             // CSR: prescaled src element offsets (s*32)
__device__ unsigned g_y2h[(size_t)NN * 32]; // half2(z,h) per (node,feature); pre-scaled by dinv
__device__ __half   g_Hh[(size_t)NN * 32];  // H in fp16, 64B rows
__device__ float    g_WT[64 * DD];          // WeffT[j][k], j: 0..31=z, 32..63=h
__device__ ull      g_beff2[32];            // packed (bz_eff, bh_eff) fp32
__device__ int      g_bsum[128];

// ---------------- helpers ------------------------------------------------------
__device__ __forceinline__ ull pack2(float a, float b) {
    ull r; asm("mov.b64 %0, {%1, %2};" : "=l"(r) : "f"(a), "f"(b)); return r;
}
__device__ __forceinline__ void unpack2(ull v, float& a, float& b) {
    asm("mov.b64 {%0, %1}, %2;" : "=f"(a), "=f"(b) : "l"(v));
}
__device__ __forceinline__ int edge_at(const void* ei, int is64, long long idx) {
    return is64 ? (int)((const long long*)ei)[idx] : ((const int*)ei)[idx];
}
__device__ __forceinline__ unsigned s2u(const void* p) {
    unsigned a;
    asm("{ .reg .u64 t; cvta.to.shared.u64 t, %1; cvt.u32.u64 %0, t; }" : "=r"(a) : "l"(p));
    return a;
}

// ---------------- prep: detect + deg init + Weff^T + beff ---------------------
__global__ void k_prep(const void* ei,
                       const float* Wz, const float* Wh,
                       const float* Lzw, const float* Lhw,
                       const float* bz, const float* bh,
                       const float* Lzb, const float* Lhb) {
    int b = blockIdx.x, t = threadIdx.x;
    if (b < 391) {
        int i = b * 256 + t;
        if (i < NN) g_deg[i] = 1;           // self loop
    } else if (b == 391) {
        __shared__ int s;
        if (t == 0) s = 1;
        __syncthreads();
        const long long* p = (const long long*)ei;
        for (int i = t; i < 4096; i += 256)
            if ((p[i] >> 32) != 0) s = 0;
        __syncthreads();
        if (t == 0) g_is64 = s;
    } else {
        int idx = (b - 392) * 256 + t;      // [0, 8192)
        int k = idx >> 6, j = idx & 63;
        float acc = 0.f;
        if (j < HID) {
            for (int m = 0; m < HID; m++) acc = fmaf(Wz[k * HID + m], Lzw[m * HID + j], acc);
        } else {
            int jj = j - HID;
            for (int m = 0; m < HID; m++) acc = fmaf(Wh[k * HID + m], Lhw[m * HID + jj], acc);
        }
        g_WT[j * DD + k] = acc;             // transposed store [j][k]
        if (b == 392 && t < 32) {
            float az = Lzb[t], ah = Lhb[t];
            for (int m = 0; m < HID; m++) {
                az = fmaf(bz[m], Lzw[m * HID + t], az);
                ah = fmaf(bh[m], Lhw[m * HID + t], ah);
            }
            g_beff2[t] = pack2(az, ah);
        }
    }
}

// ---------------- edge conversion + degree count ------------------------------
__global__ void k_deg(const void* __restrict__ ei) {
    int is64 = g_is64;
    int e = blockIdx.x * 256 + threadIdx.x;
    if (e < EE) {
        int s = edge_at(ei, is64, e);
        int d = edge_at(ei, is64, (long long)EE + e);
        g_src32[e] = s;
        g_dst32[e] = d;
        atomicAdd(&g_deg[d], 1);
    }
}

// ---------------- phase-1 scan: block-local exclusive scan of (deg-1) + dinv --
__global__ void k_scan1() {
    __shared__ int warpsums[32];
    int t = threadIdx.x, lane = t & 31, w = t >> 5;
    int i = blockIdx.x * 1024 + t;
    int dg = (i < NN) ? g_deg[i] : 1;
    if (i < NN) g_dinv[i] = rsqrtf((float)dg);
    int v = dg - 1;
    int s = v;
#pragma unroll
    for (int off = 1; off < 32; off <<= 1) {
        int tmp = __shfl_up_sync(0xffffffffu, s, off);
        if (lane >= off) s += tmp;
    }
    if (lane == 31) warpsums[w] = s;
    __syncthreads();
    if (w == 0) {
        int ws = warpsums[lane];
#pragma unroll
        for (int off = 1; off < 32; off <<= 1) {
            int tmp = __shfl_up_sync(0xffffffffu, ws, off);
            if (lane >= off) ws += tmp;
        }
        warpsums[lane] = ws;
    }
    __syncthreads();
    int incl = s + ((w == 0) ? 0 : warpsums[w - 1]);
    if (i < NN) g_off[i] = incl - v;        // block-local exclusive
    if (t == 1023) g_bsum[blockIdx.x] = incl;
}

// ---------------- phase-2: fixup; each block redundantly reduces ALL 98 sums --
#define SB 98
__global__ void k_scan3() {
    __shared__ int spref, stot;
    int t = threadIdx.x, b = blockIdx.x;
    if (t < 32) {
        int v0 = g_bsum[t];
        int v1 = g_bsum[t + 32];
        int v2 = (t + 64 < SB) ? g_bsum[t + 64] : 0;
        int v3 = (t + 96 < SB) ? g_bsum[t + 96] : 0;
        int p = ((t < b) ? v0 : 0) + ((t + 32 < b) ? v1 : 0)
              + ((t + 64 < b) ? v2 : 0) + ((t + 96 < b) ? v3 : 0);
        int q = v0 + v1 + v2 + v3;
#pragma unroll
        for (int off = 16; off; off >>= 1) {
            p += __shfl_down_sync(0xffffffffu, p, off);
            q += __shfl_down_sync(0xffffffffu, q, off);
        }
        if (t == 0) { spref = p; stot = q; }
    }
    __syncthreads();
    int i = b * 1024 + t;
    if (i < NN) {
        int o = g_off[i] + spref;
        g_off[i] = o;
        g_cur[i] = o;
    }
    if (b == SB - 1 && t == 0) g_off[NN] = stot;
}

// ---------------- HMMA node GEMM (stand-alone; 4 warp-tiles per 128-thr block) -
// y[16n,64] = x[16n,128]@Weff[128,64] per warp-tile; dinv folded; fp16 out.
// smem rows are 256B with 16B-chunk XOR swizzle: chunk' = chunk ^ (row&7).
#define GEMMB 1563
__global__ void __launch_bounds__(128) k_gemm(const float* __restrict__ x) {
    __shared__ __align__(16) __half sB[64 * 128];     // Weff fp16, swizzled (16KB)
    __shared__ __align__(16) __half sA[4][16 * 128];  // per-warp x tiles (16KB)
    int tid = threadIdx.x, wid = tid >> 5, lane = tid & 31;

    // fill B: g_WT [64][128] fp32 -> fp16 swizzled
    for (int idx = tid; idx < 2048; idx += 128) {     // 2048 float4
        int row = idx >> 5, f4 = idx & 31;
        float4 v = ((const float4*)g_WT)[idx];
        __half2 h0 = __floats2half2_rn(v.x, v.y);
        __half2 h1 = __floats2half2_rn(v.z, v.w);
        unsigned off = (unsigned)(row * 256 + (((f4 >> 1) ^ (row & 7)) << 4) + ((f4 & 1) << 3));
        *(unsigned*)((char*)sB + off)     = *(unsigned*)&h0;
        *(unsigned*)((char*)sB + off + 4) = *(unsigned*)&h1;
    }
    __syncthreads();

    int wt = blockIdx.x * 4 + wid;                    // warp-tile id
    if (wt >= 6250) return;
    int n0 = wt * 16;

    const float4* x4 = (const float4*)x;
#pragma unroll
    for (int ii = 0; ii < 16; ii++) {
        float4 v = x4[(size_t)(n0 + ii) * 32 + lane];
        __half2 h0 = __floats2half2_rn(v.x, v.y);
        __half2 h1 = __floats2half2_rn(v.z, v.w);
        unsigned off = (unsigned)(ii * 256 + (((lane >> 1) ^ (ii & 7)) << 4) + ((lane & 1) << 3));
        *(unsigned*)((char*)sA[wid] + off)     = *(unsigned*)&h0;
        *(unsigned*)((char*)sA[wid] + off + 4) = *(unsigned*)&h1;
    }
    __syncwarp();

    unsigned Af[8][4];
    unsigned sA_u = s2u(sA[wid]);
    {
        int r = lane & 15;
#pragma unroll
        for (int kt = 0; kt < 8; kt++) {
            unsigned chunk = (unsigned)(2 * kt + ((lane & 16) ? 1 : 0));
            unsigned addr = sA_u + (unsigned)(r * 256) + ((chunk ^ (unsigned)(r & 7)) << 4);
            asm volatile("ldmatrix.sync.aligned.m8n8.x4.shared.b16 {%0,%1,%2,%3}, [%4];"
                         : "=r"(Af[kt][0]), "=r"(Af[kt][1]), "=r"(Af[kt][2]), "=r"(Af[kt][3])
                         : "r"(addr));
        }
    }

    unsigned sB_u = s2u(sB);
    int g = lane >> 2, tig = lane & 3;
    int rB = lane & 7;
    unsigned bhalf = (lane & 8) ? 1u : 0u;

#pragma unroll
    for (int p = 0; p < 4; p++) {                     // z cols nt=p, h cols nt=p+4
        float Dz[4] = {0.f, 0.f, 0.f, 0.f};
        float Dh[4] = {0.f, 0.f, 0.f, 0.f};
#pragma unroll
        for (int kt = 0; kt < 8; kt++) {
            unsigned chunk = (unsigned)(2 * kt) + bhalf;
            unsigned swz = ((chunk ^ (unsigned)rB) << 4);
            unsigned az_addr = sB_u + (unsigned)((p * 8 + rB) * 256) + swz;
            unsigned ah_addr = sB_u + (unsigned)(((p + 4) * 8 + rB) * 256) + swz;
            unsigned Bz[2], Bh[2];
            asm volatile("ldmatrix.sync.aligned.m8n8.x2.shared.b16 {%0,%1}, [%2];"
                         : "=r"(Bz[0]), "=r"(Bz[1]) : "r"(az_addr));
            asm volatile("ldmatrix.sync.aligned.m8n8.x2.shared.b16 {%0,%1}, [%2];"
                         : "=r"(Bh[0]), "=r"(Bh[1]) : "r"(ah_addr));
            asm volatile(
                "mma.sync.aligned.m16n8k16.row.col.f32.f16.f16.f32 "
                "{%0,%1,%2,%3}, {%4,%5,%6,%7}, {%8,%9}, {%0,%1,%2,%3};"
                : "+f"(Dz[0]), "+f"(Dz[1]), "+f"(Dz[2]), "+f"(Dz[3])
                : "r"(Af[kt][0]), "r"(Af[kt][1]), "r"(Af[kt][2]), "r"(Af[kt][3]),
                  "r"(Bz[0]), "r"(Bz[1]));
            asm volatile(
                "mma.sync.aligned.m16n8k16.row.col.f32.f16.f16.f32 "
                "{%0,%1,%2,%3}, {%4,%5,%6,%7}, {%8,%9}, {%0,%1,%2,%3};"
                : "+f"(Dh[0]), "+f"(Dh[1]), "+f"(Dh[2]), "+f"(Dh[3])
                : "r"(Af[kt][0]), "r"(Af[kt][1]), "r"(Af[kt][2]), "r"(Af[kt][3]),
                  "r"(Bh[0]), "r"(Bh[1]));
        }
        int c0 = p * 8 + tig * 2;
        float dn0 = g_dinv[n0 + g];
        float dn1 = g_dinv[n0 + g + 8];
        __half2 a0 = __floats2half2_rn(Dz[0] * dn0, Dh[0] * dn0);
        __half2 a1 = __floats2half2_rn(Dz[1] * dn0, Dh[1] * dn0);
        __half2 b0 = __floats2half2_rn(Dz[2] * dn1, Dh[2] * dn1);
        __half2 b1 = __floats2half2_rn(Dz[3] * dn1, Dh[3] * dn1);
        unsigned ua0 = *(unsigned*)&a0, ua1 = *(unsigned*)&a1;
        unsigned ub0 = *(unsigned*)&b0, ub1 = *(unsigned*)&b1;
        *(ull*)&g_y2h[(size_t)(n0 + g) * 32 + c0]     = ((ull)ua1 << 32) | ua0;
        *(ull*)&g_y2h[(size_t)(n0 + g + 8) * 32 + c0] = ((ull)ub1 << 32) | ub0;
    }
}

// ---------------- CSR scatter (stand-alone: no smem, max occupancy) -----------
__global__ void k_scatter() {
    int e = blockIdx.x * 256 + threadIdx.x;
    if (e < EE) {
        int s = g_src32[e], d = g_dst32[e];
        int pos = atomicAdd(&g_cur[d], 1);
        g_srcs[pos] = s * 32;               // prescaled element offset into g_y2h
    }
}

// ---------------- aggregate (fp16 gathers, fp32 accum) + GRU gates → fp16 H ---
__global__ void k_agg() {
    int warp = (blockIdx.x * blockDim.x + threadIdx.x) >> 5;
    int lane = threadIdx.x & 31;
    if (warp >= NN) return;
    int n = warp;
    unsigned sv = g_y2h[(size_t)n * 32 + lane];     // self term
    float2 f = __half22float2(*(__half2*)&sv);
    float az0 = f.x, ah0 = f.y, az1 = 0.f, ah1 = 0.f;
    int beg = g_off[n], end = g_off[n + 1];
    int idx = beg;
    for (; idx + 1 < end; idx += 2) {
        unsigned v0 = g_y2h[g_srcs[idx] + lane];
        unsigned v1 = g_y2h[g_srcs[idx + 1] + lane];
        float2 f0 = __half22float2(*(__half2*)&v0);
        float2 f1 = __half22float2(*(__half2*)&v1);
        az0 += f0.x; ah0 += f0.y;
        az1 += f1.x; ah1 += f1.y;
    }
    if (idx < end) {
        unsigned v0 = g_y2h[g_srcs[idx] + lane];
        float2 f0 = __half22float2(*(__half2*)&v0);
        az0 += f0.x; ah0 += f0.y;
    }
    float dn = g_dinv[n];
    float bz, bh;
    unpack2(g_beff2[lane], bz, bh);
    float vz = (az0 + az1) * dn + bz;
    float vh = (ah0 + ah1) * dn + bh;
    float z  = 1.f / (1.f + __expf(-vz));
    float ht = tanhf(vh);
    g_Hh[(size_t)n * 32 + lane] = __float2half((1.f - z) * ht);
}

// ---------------- edge MLP via mma.sync m16n8k16 (R14-proven) -----------------
__global__ void __launch_bounds__(256) k_edge_mma(
        const float* __restrict__ w1, const float* __restrict__ b1,
        const float* __restrict__ w2, const float* __restrict__ b2,
        float* __restrict__ out) {
    __shared__ __align__(16) __half sEmb[8][16][32];
    __shared__ float sb1[32], sw2[32];
    __shared__ float sb2v;
    int tid = threadIdx.x, wid = tid >> 5, lane = tid & 31;
    if (tid < 32) { sb1[tid] = b1[tid]; sw2[tid] = w2[tid]; }
    if (tid == 0) sb2v = b2[0];

    int g = lane >> 2, tig = lane & 3;

    unsigned Bf[2][4][2];
#pragma unroll
    for (int kt = 0; kt < 2; kt++) {
#pragma unroll
        for (int nt = 0; nt < 4; nt++) {
            int n = nt * 8 + g;
            int k0 = kt * 16 + tig * 2;
            __half2 t0 = __floats2half2_rn(w1[k0 * HID + n],       w1[(k0 + 1) * HID + n]);
            __half2 t1 = __floats2half2_rn(w1[(k0 + 8) * HID + n], w1[(k0 + 9) * HID + n]);
            Bf[kt][nt][0] = *(unsigned*)&t0;
            Bf[kt][nt][1] = *(unsigned*)&t1;
        }
    }
    __syncthreads();

    int ebase = (blockIdx.x * 8 + wid) * 16;
    int er = lane >> 1, hf = lane & 1;
    {
        int e = ebase + er;
        int s = g_src32[e], d = g_dst32[e];
        const uint4* Hs = (const uint4*)(g_Hh + (size_t)s * 32) + hf * 2;
        const uint4* Hd = (const uint4*)(g_Hh + (size_t)d * 32) + hf * 2;
        uint4 sa = Hs[0], sbv = Hs[1];
        uint4 da = Hd[0], dbv = Hd[1];
        uint4 r0, r1;
        *(__half2*)&r0.x = __hmul2(*(__half2*)&sa.x, *(__half2*)&da.x);
        *(__half2*)&r0.y = __hmul2(*(__half2*)&sa.y, *(__half2*)&da.y);
        *(__half2*)&r0.z = __hmul2(*(__half2*)&sa.z, *(__half2*)&da.z);
        *(__half2*)&r0.w = __hmul2(*(__half2*)&sa.w, *(__half2*)&da.w);
        *(__half2*)&r1.x = __hmul2(*(__half2*)&sbv.x, *(__half2*)&dbv.x);
        *(__half2*)&r1.y = __hmul2(*(__half2*)&sbv.y, *(__half2*)&dbv.y);
        *(__half2*)&r1.z = __hmul2(*(__half2*)&sbv.z, *(__half2*)&dbv.z);
        *(__half2*)&r1.w = __hmul2(*(__half2*)&sbv.w, *(__half2*)&dbv.w);
        uint4* dst = (uint4*)&sEmb[wid][er][hf * 16];
        dst[0] = r0;
        dst[1] = r1;
    }
    __syncwarp();

    unsigned A0[4], A1[4];
    {
        unsigned base = s2u(&sEmb[wid][lane & 15][(lane & 16) ? 8 : 0]);
        asm volatile("ldmatrix.sync.aligned.m8n8.x4.shared.b16 {%0,%1,%2,%3}, [%4];"
                     : "=r"(A0[0]), "=r"(A0[1]), "=r"(A0[2]), "=r"(A0[3]) : "r"(base));
        asm volatile("ldmatrix.sync.aligned.m8n8.x4.shared.b16 {%0,%1,%2,%3}, [%4];"
                     : "=r"(A1[0]), "=r"(A1[1]), "=r"(A1[2]), "=r"(A1[3]) : "r"(base + 32));
    }

    float D[4][4];
#pragma unroll
    for (int nt = 0; nt < 4; nt++) {
        D[nt][0] = D[nt][1] = D[nt][2] = D[nt][3] = 0.f;
        asm volatile(
            "mma.sync.aligned.m16n8k16.row.col.f32.f16.f16.f32 "
            "{%0,%1,%2,%3}, {%4,%5,%6,%7}, {%8,%9}, {%0,%1,%2,%3};"
            : "+f"(D[nt][0]), "+f"(D[nt][1]), "+f"(D[nt][2]), "+f"(D[nt][3])
            : "r"(A0[0]), "r"(A0[1]), "r"(A0[2]), "r"(A0[3]),
              "r"(Bf[0][nt][0]), "r"(Bf[0][nt][1]));
        asm volatile(
            "mma.sync.aligned.m16n8k16.row.col.f32.f16.f16.f32 "
            "{%0,%1,%2,%3}, {%4,%5,%6,%7}, {%8,%9}, {%0,%1,%2,%3};"
            : "+f"(D[nt][0]), "+f"(D[nt][1]), "+f"(D[nt][2]), "+f"(D[nt][3])
            : "r"(A1[0]), "r"(A1[1]), "r"(A1[2]), "r"(A1[3]),
              "r"(Bf[1][nt][0]), "r"(Bf[1][nt][1]));
    }

    float l0 = 0.f, l1 = 0.f;
#pragma unroll
    for (int nt = 0; nt < 4; nt++) {
        int c0 = nt * 8 + tig * 2;
        float w20 = sw2[c0], w21 = sw2[c0 + 1];
        float bb0 = sb1[c0], bb1 = sb1[c0 + 1];
        l0 = fmaf(fmaxf(D[nt][0] + bb0, 0.f), w20, l0);
        l0 = fmaf(fmaxf(D[nt][1] + bb1, 0.f), w21, l0);
        l1 = fmaf(fmaxf(D[nt][2] + bb0, 0.f), w20, l1);
        l1 = fmaf(fmaxf(D[nt][3] + bb1, 0.f), w21, l1);
    }
    l0 += __shfl_xor_sync(0xffffffffu, l0, 1);
    l0 += __shfl_xor_sync(0xffffffffu, l0, 2);
    l1 += __shfl_xor_sync(0xffffffffu, l1, 1);
    l1 += __shfl_xor_sync(0xffffffffu, l1, 2);
    if (tig == 0) {
        out[ebase + g]     = 1.f / (1.f + __expf(-(l0 + sb2v)));
        out[ebase + g + 8] = 1.f / (1.f + __expf(-(l1 + sb2v)));
    }
}

// ---------------- launch ------------------------------------------------------
extern "C" void kernel_launch(void* const* d_in, const int* in_sizes, int n_in,
                              void* d_out, int out_size) {
    const float* x   = (const float*)d_in[0];
    const void*  ei  = d_in[1];
    const float* Wz  = (const float*)d_in[2];
    const float* bz  = (const float*)d_in[3];
    const float* Wh  = (const float*)d_in[6];
    const float* bh  = (const float*)d_in[7];
    const float* Lzw = (const float*)d_in[8];
    const float* Lzb = (const float*)d_in[9];
    const float* Lhw = (const float*)d_in[12];
    const float* Lhb = (const float*)d_in[13];
    const float* w1  = (const float*)d_in[14];
    const float* b1  = (const float*)d_in[15];
    const float* w2  = (const float*)d_in[16];
    const float* b2  = (const float*)d_in[17];
    float* out = (float*)d_out;

    k_prep<<<424, 256>>>(ei, Wz, Wh, Lzw, Lhw, bz, bh, Lzb, Lhb);
    k_deg<<<6250, 256>>>(ei);
    k_scan1<<<98, 1024>>>();
    k_scan3<<<SB, 1024>>>();
    k_gemm<<<GEMMB, 128>>>(x);
    k_scatter<<<6250, 256>>>();
    k_agg<<<(NN * 32 + 255) / 256, 256>>>();
    k_edge_mma<<<EE / 128, 256>>>(w1, b1, w2, b2, out);
}